// round 2
// baseline (speedup 1.0000x reference)
#include <cuda_runtime.h>
#include <cuda_bf16.h>
#include <math.h>

// ---------------- Problem constants ----------------
#define L       2048          // sequence length (BATCH=1)
#define DMODEL  1024
#define DINNER  2048
#define DSTATE  16
#define DCONV   4

// ---------------- Scratch (device globals; no allocs allowed) ----------------
__device__ float g_xz   [L * 2 * DINNER];   // [L, 4096]  in-proj output (x_inner | z)
__device__ float g_xssm [L * DINNER];       // [L, 2048]  conv+silu output
__device__ float g_dt   [L * DINNER];       // [L, 2048]  softplus(dt)
__device__ float g_bc   [L * 2 * DSTATE];   // [L, 32]    (B | C)
__device__ float g_y    [L * DINNER];       // [L, 2048]  gated scan output

// ---------------- SGEMM: C[M,N] = A[M,K] * B[N,K]^T  (+ epilogue) ----------------
// EPI: 0 = none, 1 = softplus(acc + bias[n]), 2 = acc + resid[m*N+n]
#define BM 128
#define BN 128
#define BK 8
#define TM 8
#define TN 8

template<int EPI>
__global__ __launch_bounds__(256)
void sgemm_tn(int M, int N, int K,
              const float* __restrict__ A,   // [M,K] row-major
              const float* __restrict__ B,   // [N,K] row-major
              float*       __restrict__ C,   // [M,N] row-major
              const float* __restrict__ bias,
              const float* __restrict__ resid)
{
    __shared__ float As[BK][BM];
    __shared__ float Bs[BK][BN];

    const int bm  = blockIdx.y * BM;
    const int bn  = blockIdx.x * BN;
    const int tid = threadIdx.x;

    // global->shared load mapping: one float4 from A and one from B per k-tile
    const int lrow = tid >> 1;          // 0..127 (row within tile)
    const int lcol = (tid & 1) << 2;    // 0 or 4 (k offset)

    // compute mapping: 16x16 thread grid of 8x8 micro-tiles
    const int tm = (tid >> 4) << 3;     // 0..120
    const int tn = (tid & 15) << 3;     // 0..120

    const float* Aptr = A + (size_t)bm * K;
    const float* Bptr = B + (size_t)bn * K;

    float acc[TM][TN];
#pragma unroll
    for (int i = 0; i < TM; i++)
#pragma unroll
        for (int j = 0; j < TN; j++) acc[i][j] = 0.f;

    for (int k0 = 0; k0 < K; k0 += BK) {
        float4 av = *(const float4*)(Aptr + (size_t)lrow * K + k0 + lcol);
        float4 bv = *(const float4*)(Bptr + (size_t)lrow * K + k0 + lcol);
        As[lcol + 0][lrow] = av.x;
        As[lcol + 1][lrow] = av.y;
        As[lcol + 2][lrow] = av.z;
        As[lcol + 3][lrow] = av.w;
        Bs[lcol + 0][lrow] = bv.x;
        Bs[lcol + 1][lrow] = bv.y;
        Bs[lcol + 2][lrow] = bv.z;
        Bs[lcol + 3][lrow] = bv.w;
        __syncthreads();

#pragma unroll
        for (int kk = 0; kk < BK; kk++) {
            float ra[TM], rb[TN];
#pragma unroll
            for (int i = 0; i < TM; i += 4) {
                float4 v = *(const float4*)&As[kk][tm + i];
                ra[i+0] = v.x; ra[i+1] = v.y; ra[i+2] = v.z; ra[i+3] = v.w;
            }
#pragma unroll
            for (int j = 0; j < TN; j += 4) {
                float4 v = *(const float4*)&Bs[kk][tn + j];
                rb[j+0] = v.x; rb[j+1] = v.y; rb[j+2] = v.z; rb[j+3] = v.w;
            }
#pragma unroll
            for (int i = 0; i < TM; i++)
#pragma unroll
                for (int j = 0; j < TN; j++)
                    acc[i][j] += ra[i] * rb[j];
        }
        __syncthreads();
    }

#pragma unroll
    for (int i = 0; i < TM; i++) {
        const int m = bm + tm + i;
#pragma unroll
        for (int j = 0; j < TN; j++) {
            const int n = bn + tn + j;
            float v = acc[i][j];
            if (EPI == 1) {
                v += bias[n];
                v = (v > 20.f) ? v : log1pf(__expf(v));   // softplus
            } else if (EPI == 2) {
                v += resid[(size_t)m * N + n];
            }
            C[(size_t)m * N + n] = v;
        }
    }
}

// ---------------- Conv (depthwise causal, k=4) + SiLU ----------------
__global__ __launch_bounds__(256)
void conv_silu_kernel(const float* __restrict__ conv_w,   // [DINNER, 1, 4]
                      const float* __restrict__ conv_b)   // [DINNER]
{
    int idx = blockIdx.x * blockDim.x + threadIdx.x;      // over L*DINNER
    int d = idx & (DINNER - 1);
    int t = idx >> 11;                                    // DINNER = 2048 = 2^11
    float w0 = conv_w[d * 4 + 0];
    float w1 = conv_w[d * 4 + 1];
    float w2 = conv_w[d * 4 + 2];
    float w3 = conv_w[d * 4 + 3];
    float s = conv_b[d];
    // x_inner[t', d] = g_xz[t' * 4096 + d]
    if (t >= 3) s += g_xz[(size_t)(t - 3) * (2 * DINNER) + d] * w0;
    if (t >= 2) s += g_xz[(size_t)(t - 2) * (2 * DINNER) + d] * w1;
    if (t >= 1) s += g_xz[(size_t)(t - 1) * (2 * DINNER) + d] * w2;
    s += g_xz[(size_t)t * (2 * DINNER) + d] * w3;
    // silu
    g_xssm[(size_t)t * DINNER + d] = s / (1.f + __expf(-s));
}

// ---------------- x_dbl = x_ssm @ W_x^T  ->  g_bc [L, 32] ----------------
__global__ __launch_bounds__(256)
void xdbl_kernel(const float* __restrict__ W_x)           // [32, DINNER]
{
    const int m = blockIdx.x;                             // row 0..L-1
    const int tid = threadIdx.x;
    __shared__ float xrow[DINNER];
    for (int i = tid; i < DINNER; i += 256)
        xrow[i] = g_xssm[(size_t)m * DINNER + i];
    __syncthreads();

    const int n = tid >> 3;       // 0..31 output index
    const int j = tid & 7;        // 8-thread reduction group
    float acc = 0.f;
    const float* w = W_x + (size_t)n * DINNER;
    for (int k = j; k < DINNER; k += 8)
        acc += xrow[k] * w[k];
    acc += __shfl_down_sync(0xffffffffu, acc, 4, 8);
    acc += __shfl_down_sync(0xffffffffu, acc, 2, 8);
    acc += __shfl_down_sync(0xffffffffu, acc, 1, 8);
    if (j == 0) g_bc[(size_t)m * (2 * DSTATE) + n] = acc;
}

// ---------------- Selective scan + gating: warp per channel ----------------
__global__ __launch_bounds__(256)
void scan_kernel(const float* __restrict__ A_log,   // [DINNER, DSTATE]
                 const float* __restrict__ D_param) // [DINNER]
{
    const int warp = (blockIdx.x * blockDim.x + threadIdx.x) >> 5;
    const int lane = threadIdx.x & 31;
    if (warp >= DINNER) return;
    const int d = warp;
    const bool act = lane < DSTATE;

    const float a  = act ? -expf(A_log[d * DSTATE + lane]) : 0.f;
    const float Dv = D_param[d];
    float h = 0.f;

    for (int t = 0; t < L; t++) {
        const float dtv = g_dt[(size_t)t * DINNER + d];
        const float xv  = g_xssm[(size_t)t * DINNER + d];
        const float bv  = act ? g_bc[(size_t)t * (2 * DSTATE) + lane] : 0.f;
        const float cv  = act ? g_bc[(size_t)t * (2 * DSTATE) + DSTATE + lane] : 0.f;

        const float e = __expf(dtv * a);
        h = e * h + bv * (dtv * xv);
        float p = h * cv;
        p += __shfl_down_sync(0xffffffffu, p, 8);
        p += __shfl_down_sync(0xffffffffu, p, 4);
        p += __shfl_down_sync(0xffffffffu, p, 2);
        p += __shfl_down_sync(0xffffffffu, p, 1);
        if (lane == 0) {
            const float zv = g_xz[(size_t)t * (2 * DINNER) + DINNER + d];
            const float silu_z = zv / (1.f + __expf(-zv));
            g_y[(size_t)t * DINNER + d] = (p + Dv * xv) * silu_z;
        }
    }
}

// ---------------- Launch ----------------
extern "C" void kernel_launch(void* const* d_in, const int* in_sizes, int n_in,
                              void* d_out, int out_size)
{
    const float* x      = (const float*)d_in[0];
    const float* W_in   = (const float*)d_in[1];
    const float* conv_w = (const float*)d_in[2];
    const float* conv_b = (const float*)d_in[3];
    const float* A_log  = (const float*)d_in[4];
    const float* D_prm  = (const float*)d_in[5];
    const float* W_x    = (const float*)d_in[6];
    const float* W_dt   = (const float*)d_in[7];
    const float* b_dt   = (const float*)d_in[8];
    const float* W_out  = (const float*)d_in[9];
    float* out = (float*)d_out;

    float *p_xz, *p_xssm, *p_dt, *p_y;
    cudaGetSymbolAddress((void**)&p_xz,   g_xz);
    cudaGetSymbolAddress((void**)&p_xssm, g_xssm);
    cudaGetSymbolAddress((void**)&p_dt,   g_dt);
    cudaGetSymbolAddress((void**)&p_y,    g_y);

    // K1: xz = x @ W_in^T   [2048, 4096], K=1024
    sgemm_tn<0><<<dim3((2 * DINNER) / BN, L / BM), 256>>>(
        L, 2 * DINNER, DMODEL, x, W_in, p_xz, nullptr, nullptr);

    // K2: causal depthwise conv + silu -> x_ssm
    conv_silu_kernel<<<(L * DINNER) / 256, 256>>>(conv_w, conv_b);

    // K3: dt = softplus(x_ssm @ W_dt^T + b_dt)   [2048, 2048], K=2048
    sgemm_tn<1><<<dim3(DINNER / BN, L / BM), 256>>>(
        L, DINNER, DINNER, p_xssm, W_dt, p_dt, b_dt, nullptr);

    // K4: x_dbl = x_ssm @ W_x^T -> (B | C)   [2048, 32]
    xdbl_kernel<<<L, 256>>>(W_x);

    // K5: selective scan + D skip + silu(z) gate -> y
    scan_kernel<<<(DINNER * 32) / 256, 256>>>(A_log, D_prm);

    // K6: out = y @ W_out^T + x   [2048, 1024], K=2048
    sgemm_tn<2><<<dim3(DMODEL / BN, L / BM), 256>>>(
        L, DMODEL, DINNER, p_y, W_out, out, nullptr, x);
}

// round 5
// speedup vs baseline: 2.2669x; 2.2669x over previous
#include <cuda_runtime.h>
#include <cuda_bf16.h>
#include <math.h>
#include <stdint.h>

// ---------------- Problem constants ----------------
#define L_SEQ   2048
#define DMODEL  1024
#define DINNER  2048
#define DSTATE  16

// ---------------- Scratch (device globals; no allocs allowed) ----------------
__device__ float g_xz   [L_SEQ * 2 * DINNER];
__device__ float g_xssm [L_SEQ * DINNER];
__device__ float g_dt   [L_SEQ * DINNER];
__device__ float g_bc   [L_SEQ * 2 * DSTATE];

__device__ __nv_bfloat16 g_x_bf   [L_SEQ * DMODEL];
__device__ __nv_bfloat16 g_Win_bf [2 * DINNER * DMODEL];
__device__ __nv_bfloat16 g_Wdt_bf [DINNER * DINNER];
__device__ __nv_bfloat16 g_Wx_bf  [128 * DINNER];
__device__ __nv_bfloat16 g_Wout_bf[DMODEL * DINNER];
__device__ __nv_bfloat16 g_xssm_bf[L_SEQ * DINNER];
__device__ __nv_bfloat16 g_y_bf   [L_SEQ * DINNER];

// ---------------- PTX helpers (base ISA only) ----------------
__device__ __forceinline__ uint32_t s2u(const void* p) {
    uint32_t a;
    asm("{ .reg .u64 t; cvta.to.shared.u64 t, %1; cvt.u32.u64 %0, t; }"
        : "=r"(a) : "l"(p));
    return a;
}
__device__ __forceinline__ void ldsm_x4(uint32_t& r0, uint32_t& r1,
                                        uint32_t& r2, uint32_t& r3, uint32_t addr) {
    asm volatile("ldmatrix.sync.aligned.m8n8.x4.shared.b16 {%0,%1,%2,%3}, [%4];"
                 : "=r"(r0), "=r"(r1), "=r"(r2), "=r"(r3) : "r"(addr));
}
__device__ __forceinline__ void mma16816(float& d0, float& d1, float& d2, float& d3,
                                         uint32_t a0, uint32_t a1, uint32_t a2, uint32_t a3,
                                         uint32_t b0, uint32_t b1) {
    asm volatile(
        "mma.sync.aligned.m16n8k16.row.col.f32.bf16.bf16.f32 "
        "{%0,%1,%2,%3}, {%4,%5,%6,%7}, {%8,%9}, {%0,%1,%2,%3};"
        : "+f"(d0), "+f"(d1), "+f"(d2), "+f"(d3)
        : "r"(a0), "r"(a1), "r"(a2), "r"(a3), "r"(b0), "r"(b1));
}

// ---------------- HMMA bf16 GEMM: C[M,N] = A[M,K] * B[N,K]^T (+ epilogue) ----
// BM=BN=128, BK=32; 256 threads = 8 warps (4 M x 2 N), warp tile 32x64.
// Single smem buffer; proven R2 load structure: LDG->regs, STS, sync, compute,
// with next tile's LDGs issued BEFORE the mma loop so latency hides under HMMA.
// Smem rows: 32 bf16 (64B) payload at 80B stride -> conflict-free ldmatrix.
// EPI: 0 plain, 1 softplus(acc+bias[n]), 2 acc+resid[m*ldc+n],
//      3 store only cols<32 into C[m*32+col] (x_dbl slice)
#define ROWB       80
#define TILE_BYTES (128 * ROWB)          // 10240 per operand

template<int EPI>
__global__ __launch_bounds__(256)
void mma_gemm(int N, int K,
              const __nv_bfloat16* __restrict__ A,
              const __nv_bfloat16* __restrict__ B,
              float* __restrict__ C, int ldc,
              const float* __restrict__ bias,
              const float* __restrict__ resid)
{
    __shared__ __align__(16) char smem[2 * TILE_BYTES];   // A tile | B tile (20 KB)

    const int tid    = threadIdx.x;
    const int wid    = tid >> 5;
    const int lane   = tid & 31;
    const int warp_m = wid & 3;
    const int warp_n = wid >> 2;
    const int bm = blockIdx.y * 128;
    const int bn = blockIdx.x * 128;

    const uint32_t sa = s2u(smem);
    const uint32_t sb = sa + TILE_BYTES;
    const __nv_bfloat16* Abase = A + (size_t)bm * K;
    const __nv_bfloat16* Bbase = B + (size_t)bn * K;

    // per-thread load slots: 2 x 16B chunks of A and of B per k-tile
    const int r0 = tid >> 2,          c0 = tid & 3;          // slot 0
    const int r1 = (256 + tid) >> 2,  c1 = (256 + tid) & 3;  // slot 1

    uint4 ra0, ra1, rb0, rb1;
    auto ldgs = [&](int c) {
        const size_t k0 = (size_t)c * 32;
        ra0 = *(const uint4*)(Abase + (size_t)r0 * K + k0 + c0 * 8);
        ra1 = *(const uint4*)(Abase + (size_t)r1 * K + k0 + c1 * 8);
        rb0 = *(const uint4*)(Bbase + (size_t)r0 * K + k0 + c0 * 8);
        rb1 = *(const uint4*)(Bbase + (size_t)r1 * K + k0 + c1 * 8);
    };

    float acc[2][8][4];
#pragma unroll
    for (int mi = 0; mi < 2; mi++)
#pragma unroll
        for (int ni = 0; ni < 8; ni++)
#pragma unroll
            for (int r = 0; r < 4; r++) acc[mi][ni][r] = 0.f;

    const int nc = K >> 5;
    ldgs(0);

    const int lr = lane & 15;
    const int lc = (lane >> 4) & 1;

    for (int c = 0; c < nc; ++c) {
        __syncthreads();                       // previous compute done reading smem
        *(uint4*)(smem + r0 * ROWB + c0 * 16)              = ra0;
        *(uint4*)(smem + r1 * ROWB + c1 * 16)              = ra1;
        *(uint4*)(smem + TILE_BYTES + r0 * ROWB + c0 * 16) = rb0;
        *(uint4*)(smem + TILE_BYTES + r1 * ROWB + c1 * 16) = rb1;
        __syncthreads();

        if (c + 1 < nc) ldgs(c + 1);           // overlap next LDGs with mma below

#pragma unroll
        for (int ks = 0; ks < 2; ks++) {
            const int colb = ks * 32 + lc * 16;
            uint32_t a[2][4];
#pragma unroll
            for (int mi = 0; mi < 2; mi++) {
                uint32_t addr = sa + (warp_m * 32 + mi * 16 + lr) * ROWB + colb;
                ldsm_x4(a[mi][0], a[mi][1], a[mi][2], a[mi][3], addr);
            }
            uint32_t b[8][2];
#pragma unroll
            for (int n2 = 0; n2 < 4; n2++) {
                uint32_t t0, t1, t2, t3;
                uint32_t addr = sb + (warp_n * 64 + n2 * 16 + lr) * ROWB + colb;
                ldsm_x4(t0, t1, t2, t3, addr);
                b[2 * n2 + 0][0] = t0; b[2 * n2 + 0][1] = t2;
                b[2 * n2 + 1][0] = t1; b[2 * n2 + 1][1] = t3;
            }
#pragma unroll
            for (int mi = 0; mi < 2; mi++)
#pragma unroll
                for (int ni = 0; ni < 8; ni++)
                    mma16816(acc[mi][ni][0], acc[mi][ni][1],
                             acc[mi][ni][2], acc[mi][ni][3],
                             a[mi][0], a[mi][1], a[mi][2], a[mi][3],
                             b[ni][0], b[ni][1]);
        }
    }

    // ---------------- epilogue ----------------
    const int row_in = (lane >> 2);
    const int col_in = (lane & 3) * 2;

#pragma unroll
    for (int mi = 0; mi < 2; mi++) {
#pragma unroll
        for (int ni = 0; ni < 8; ni++) {
            const int m0  = bm + warp_m * 32 + mi * 16 + row_in;
            const int col = bn + warp_n * 64 + ni * 8 + col_in;
            float v[4] = {acc[mi][ni][0], acc[mi][ni][1],
                          acc[mi][ni][2], acc[mi][ni][3]};
            if (EPI == 1) {
                const float bi0 = __ldg(bias + col);
                const float bi1 = __ldg(bias + col + 1);
                v[0] += bi0; v[1] += bi1; v[2] += bi0; v[3] += bi1;
#pragma unroll
                for (int r = 0; r < 4; r++)
                    v[r] = (v[r] > 20.f) ? v[r] : log1pf(__expf(v[r]));
            } else if (EPI == 2) {
                const float2 q0 = *(const float2*)(resid + (size_t)m0 * ldc + col);
                const float2 q1 = *(const float2*)(resid + (size_t)(m0 + 8) * ldc + col);
                v[0] += q0.x; v[1] += q0.y; v[2] += q1.x; v[3] += q1.y;
            }
            if (EPI == 3) {
                if (col < 32) {
                    float2 o0; o0.x = v[0]; o0.y = v[1];
                    float2 o1; o1.x = v[2]; o1.y = v[3];
                    *(float2*)(C + (size_t)m0 * 32 + col)       = o0;
                    *(float2*)(C + (size_t)(m0 + 8) * 32 + col) = o1;
                }
            } else {
                float2 o0; o0.x = v[0]; o0.y = v[1];
                float2 o1; o1.x = v[2]; o1.y = v[3];
                *(float2*)(C + (size_t)m0 * ldc + col)       = o0;
                *(float2*)(C + (size_t)(m0 + 8) * ldc + col) = o1;
            }
        }
    }
}

// ---------------- fp32 -> bf16 ----------------
__global__ __launch_bounds__(256)
void f2bf_kernel(const float4* __restrict__ in, __nv_bfloat162* __restrict__ out, int n4)
{
    int i = blockIdx.x * blockDim.x + threadIdx.x;
    if (i >= n4) return;
    float4 v = in[i];
    out[2 * i + 0] = __float22bfloat162_rn(make_float2(v.x, v.y));
    out[2 * i + 1] = __float22bfloat162_rn(make_float2(v.z, v.w));
}

__global__ __launch_bounds__(256)
void pad_wx_kernel(const float* __restrict__ W_x)
{
    int idx = blockIdx.x * blockDim.x + threadIdx.x;    // over 128*2048
    int row = idx >> 11;
    float v = (row < 2 * DSTATE) ? W_x[idx] : 0.f;
    g_Wx_bf[idx] = __float2bfloat16(v);
}

// ---------------- Conv (depthwise causal, k=4) + SiLU ----------------
__global__ __launch_bounds__(256)
void conv_silu_kernel(const float* __restrict__ conv_w, const float* __restrict__ conv_b)
{
    int idx = blockIdx.x * blockDim.x + threadIdx.x;    // over L*DINNER
    int d = idx & (DINNER - 1);
    int t = idx >> 11;
    float w0 = conv_w[d * 4 + 0];
    float w1 = conv_w[d * 4 + 1];
    float w2 = conv_w[d * 4 + 2];
    float w3 = conv_w[d * 4 + 3];
    float s = conv_b[d];
    if (t >= 3) s += g_xz[(size_t)(t - 3) * (2 * DINNER) + d] * w0;
    if (t >= 2) s += g_xz[(size_t)(t - 2) * (2 * DINNER) + d] * w1;
    if (t >= 1) s += g_xz[(size_t)(t - 1) * (2 * DINNER) + d] * w2;
    s += g_xz[(size_t)t * (2 * DINNER) + d] * w3;
    float v = s / (1.f + __expf(-s));
    g_xssm[(size_t)t * DINNER + d] = v;
    g_xssm_bf[(size_t)t * DINNER + d] = __float2bfloat16(v);
}

// ---------------- Selective scan + D skip + silu(z) gate ----------------
__global__ __launch_bounds__(256)
void scan_kernel(const float* __restrict__ A_log, const float* __restrict__ D_param)
{
    const int warp = (blockIdx.x * blockDim.x + threadIdx.x) >> 5;
    const int lane = threadIdx.x & 31;
    const int d = warp;
    const bool act = lane < DSTATE;

    const float a  = act ? -__expf(A_log[d * DSTATE + lane]) : 0.f;
    const float Dv = D_param[d];
    float h = 0.f;

    for (int t = 0; t < L_SEQ; t += 2) {
        const float dt0 = g_dt[(size_t)t * DINNER + d];
        const float x0  = g_xssm[(size_t)t * DINNER + d];
        const float dt1 = g_dt[(size_t)(t + 1) * DINNER + d];
        const float x1  = g_xssm[(size_t)(t + 1) * DINNER + d];
        float b0 = 0.f, c0 = 0.f, b1 = 0.f, c1 = 0.f;
        if (act) {
            b0 = g_bc[t * 32 + lane];
            c0 = g_bc[t * 32 + 16 + lane];
            b1 = g_bc[(t + 1) * 32 + lane];
            c1 = g_bc[(t + 1) * 32 + 16 + lane];
        }
        const float e0 = __expf(dt0 * a);
        const float e1 = __expf(dt1 * a);
        h = e0 * h + b0 * (dt0 * x0);
        float p0 = h * c0;
        h = e1 * h + b1 * (dt1 * x1);
        float p1 = h * c1;
#pragma unroll
        for (int k = 8; k >= 1; k >>= 1) {
            p0 += __shfl_down_sync(0xffffffffu, p0, k, 16);
            p1 += __shfl_down_sync(0xffffffffu, p1, k, 16);
        }
        if (lane == 0) {
            float z0 = g_xz[(size_t)t * (2 * DINNER) + DINNER + d];
            float z1 = g_xz[(size_t)(t + 1) * (2 * DINNER) + DINNER + d];
            float y0 = (p0 + Dv * x0) * (z0 / (1.f + __expf(-z0)));
            float y1 = (p1 + Dv * x1) * (z1 / (1.f + __expf(-z1)));
            g_y_bf[(size_t)t * DINNER + d]       = __float2bfloat16(y0);
            g_y_bf[(size_t)(t + 1) * DINNER + d] = __float2bfloat16(y1);
        }
    }
}

// ---------------- Launch ----------------
extern "C" void kernel_launch(void* const* d_in, const int* in_sizes, int n_in,
                              void* d_out, int out_size)
{
    const float* x      = (const float*)d_in[0];
    const float* W_in   = (const float*)d_in[1];
    const float* conv_w = (const float*)d_in[2];
    const float* conv_b = (const float*)d_in[3];
    const float* A_log  = (const float*)d_in[4];
    const float* D_prm  = (const float*)d_in[5];
    const float* W_x    = (const float*)d_in[6];
    const float* W_dt   = (const float*)d_in[7];
    const float* b_dt   = (const float*)d_in[8];
    const float* W_out  = (const float*)d_in[9];
    float* out = (float*)d_out;

    float *p_xz, *p_dt, *p_bc;
    __nv_bfloat16 *p_x_bf, *p_Win_bf, *p_Wdt_bf, *p_Wx_bf, *p_Wout_bf, *p_xssm_bf, *p_y_bf;
    cudaGetSymbolAddress((void**)&p_xz,      g_xz);
    cudaGetSymbolAddress((void**)&p_dt,      g_dt);
    cudaGetSymbolAddress((void**)&p_bc,      g_bc);
    cudaGetSymbolAddress((void**)&p_x_bf,    g_x_bf);
    cudaGetSymbolAddress((void**)&p_Win_bf,  g_Win_bf);
    cudaGetSymbolAddress((void**)&p_Wdt_bf,  g_Wdt_bf);
    cudaGetSymbolAddress((void**)&p_Wx_bf,   g_Wx_bf);
    cudaGetSymbolAddress((void**)&p_Wout_bf, g_Wout_bf);
    cudaGetSymbolAddress((void**)&p_xssm_bf, g_xssm_bf);
    cudaGetSymbolAddress((void**)&p_y_bf,    g_y_bf);

    f2bf_kernel<<<(L_SEQ * DMODEL / 4) / 256, 256>>>(
        (const float4*)x, (__nv_bfloat162*)p_x_bf, L_SEQ * DMODEL / 4);
    f2bf_kernel<<<(2 * DINNER * DMODEL / 4) / 256, 256>>>(
        (const float4*)W_in, (__nv_bfloat162*)p_Win_bf, 2 * DINNER * DMODEL / 4);
    f2bf_kernel<<<(DINNER * DINNER / 4) / 256, 256>>>(
        (const float4*)W_dt, (__nv_bfloat162*)p_Wdt_bf, DINNER * DINNER / 4);
    f2bf_kernel<<<(DMODEL * DINNER / 4) / 256, 256>>>(
        (const float4*)W_out, (__nv_bfloat162*)p_Wout_bf, DMODEL * DINNER / 4);
    pad_wx_kernel<<<(128 * DINNER) / 256, 256>>>(W_x);

    // K1: xz = x @ W_in^T   [2048, 4096], K=1024
    mma_gemm<0><<<dim3(32, 16), 256>>>(
        4096, 1024, p_x_bf, p_Win_bf, p_xz, 4096, nullptr, nullptr);

    // K2: causal depthwise conv + silu
    conv_silu_kernel<<<(L_SEQ * DINNER) / 256, 256>>>(conv_w, conv_b);

    // K3: dt = softplus(x_ssm @ W_dt^T + b_dt)   [2048, 2048], K=2048
    mma_gemm<1><<<dim3(16, 16), 256>>>(
        2048, 2048, p_xssm_bf, p_Wdt_bf, p_dt, 2048, b_dt, nullptr);

    // K4: (B|C) = x_ssm @ W_x^T (padded to 128 rows), store first 32 cols
    mma_gemm<3><<<dim3(1, 16), 256>>>(
        128, 2048, p_xssm_bf, p_Wx_bf, p_bc, 32, nullptr, nullptr);

    // K5: selective scan + gate
    scan_kernel<<<(DINNER * 32) / 256, 256>>>(A_log, D_prm);

    // K6: out = y @ W_out^T + x   [2048, 1024], K=2048
    mma_gemm<2><<<dim3(8, 16), 256>>>(
        1024, 2048, p_y_bf, p_Wout_bf, out, 1024, nullptr, x);
}